// round 8
// baseline (speedup 1.0000x reference)
#include <cuda_runtime.h>
#include <cuda_fp16.h>
#include <cstdint>
#include <cstddef>

#define ND 4
#define NB 128
#define NL 200
#define DIM 512
#define M_TOTAL (ND * NB * NL)   // 102400
#define LN_EPS 1e-8f

// fused GEMM tiling
#define BM 64
#define BN 128
#define BK 32
#define NKT (DIM / BK)           // 16 per n-block
#define NNB (DIM / BN)           // 4 n-blocks
#define NKTG (NKT * NNB)         // 64 total k-iters
#define ROW_B 80                 // padded smem row stride (64B data + 16B)
#define A_STAGE (BM * ROW_B)     // 5120
#define B_STAGE (BN * ROW_B)     // 10240
#define NSTAGE 4
#define STG_BYTES (NSTAGE * (A_STAGE + B_STAGE))  // 61440
#define RES_STRIDE 520           // words per row (512 + 8 pad)
#define RES_BYTES (BM * RES_STRIDE * 4)           // 133120
#define SM_BIAS   (STG_BYTES + RES_BYTES)
#define SM_GAMMA  (SM_BIAS + 2048)
#define SM_BETA   (SM_GAMMA + 2048)
#define SMEM_BYTES (SM_BETA + 2048)               // 200704

// per-expert capacity (mean cnt ~20480, sd ~128)
#define CAP 24576
#define MBLK (CAP / BM)          // 384

// -------- device scratch (static, allocation-guard-safe) --------
__device__ int g_count[5];               // 4 experts + pad bucket
__device__ int g_list[5][M_TOTAL];
__device__ __half g_xh[ND][(size_t)CAP * DIM];   // 96 MB compacted fp16 X
__device__ __half g_wh[ND * DIM * DIM];          // 2 MB fp16 W

// -------- helpers --------
__device__ __forceinline__ unsigned pack_h2(float lo, float hi) {
    unsigned d;
    asm("cvt.rn.f16x2.f32 %0, %1, %2;" : "=r"(d) : "f"(hi), "f"(lo));
    return d;
}
__device__ __forceinline__ uint32_t smem_u32(const void* p) {
    uint32_t a;
    asm("{ .reg .u64 t; cvta.to.shared.u64 t, %1; cvt.u32.u64 %0, t; }" : "=r"(a) : "l"(p));
    return a;
}
#define CP_ASYNC16(dst, src) \
    asm volatile("cp.async.cg.shared.global [%0], [%1], 16;" :: "r"(dst), "l"(src) : "memory")
#define CP_COMMIT() asm volatile("cp.async.commit_group;" ::: "memory")
#define CP_WAIT2()  asm volatile("cp.async.wait_group 2;" ::: "memory")

#define LDMX4(r0, r1, r2, r3, a) \
    asm volatile("ldmatrix.sync.aligned.m8n8.x4.shared.b16 {%0,%1,%2,%3}, [%4];" \
        : "=r"(r0), "=r"(r1), "=r"(r2), "=r"(r3) : "r"(a))

__device__ __forceinline__ void mma_f16(float* d, const unsigned* a, const unsigned* b) {
    asm("mma.sync.aligned.m16n8k16.row.col.f32.f16.f16.f32 "
        "{%0,%1,%2,%3}, {%4,%5,%6,%7}, {%8,%9}, {%0,%1,%2,%3};"
        : "+f"(d[0]), "+f"(d[1]), "+f"(d[2]), "+f"(d[3])
        : "r"(a[0]), "r"(a[1]), "r"(a[2]), "r"(a[3]),
          "r"(b[0]), "r"(b[1]));
}

// ================= kernel 0: reset =================
__global__ void reset_kernel() {
    if (threadIdx.x < 5) g_count[threadIdx.x] = 0;
}

// ================= kernel 1: routing (experts + pad bucket) =================
__global__ void route_kernel(const int* __restrict__ lg_dom) {
    int m = blockIdx.x * blockDim.x + threadIdx.x;
    if (m >= M_TOTAL) return;
    int i = m / (NB * NL);
    int r = m - i * (NB * NL);
    int b = r / NL;
    int l = r - b * NL;
    int lg = lg_dom[b * (ND * NL) + i * NL + l];
    int bucket = (lg > 0) ? (lg - 1) : 4;
    int slot = atomicAdd(&g_count[bucket], 1);
    g_list[bucket][slot] = m;
}

// ================= kernel 2a: convert W -> fp16 =================
__global__ void wconv_kernel(const float* __restrict__ W) {
    int t = blockIdx.x * blockDim.x + threadIdx.x;   // 8 floats each
    const float4 v0 = ((const float4*)W)[t * 2];
    const float4 v1 = ((const float4*)W)[t * 2 + 1];
    uint4 o;
    o.x = pack_h2(v0.x, v0.y);
    o.y = pack_h2(v0.z, v0.w);
    o.z = pack_h2(v1.x, v1.y);
    o.w = pack_h2(v1.z, v1.w);
    ((uint4*)g_wh)[t] = o;
}

// ================= kernel 2b: gather + compact + convert X -> fp16 =================
__global__ void xconv_kernel(const float* __restrict__ X) {
    const int e = blockIdx.y;
    const int cnt = g_count[e];
    const int rcap = (cnt + BM - 1) & ~(BM - 1);
    const int t = blockIdx.x * blockDim.x + threadIdx.x;  // r * 64 + c
    const int r = t >> 6;
    if (r >= rcap) return;
    const int c = t & 63;
    uint4 o;
    if (r < cnt) {
        const float4* src = (const float4*)(X + (size_t)g_list[e][r] * DIM + c * 8);
        float4 v0 = src[0], v1 = src[1];
        o.x = pack_h2(v0.x, v0.y);
        o.y = pack_h2(v0.z, v0.w);
        o.z = pack_h2(v1.x, v1.y);
        o.w = pack_h2(v1.z, v1.w);
    } else {
        o = make_uint4(0u, 0u, 0u, 0u);
    }
    *(uint4*)(&g_xh[e][(size_t)r * DIM + c * 8]) = o;
}

// ================= kernel 3: fused GEMM + LayerNorm + logits =================
// Each CTA: 64 tokens x full N=512 (4 n-blocks), result tile held in smem,
// then warp-per-row LN + Y store + pos/neg logit dots. One Y write, no re-read.
__global__ void __launch_bounds__(256, 1)
fused_kernel(const float* __restrict__ Bias, const float* __restrict__ emb,
             const float* __restrict__ gamma, const float* __restrict__ beta,
             const int* __restrict__ pos_idx, const int* __restrict__ neg_idx,
             float* __restrict__ Y, float* __restrict__ pos_out,
             float* __restrict__ neg_out)
{
    const int e   = blockIdx.y;
    const int cnt = g_count[e];
    const int m0  = blockIdx.x * BM;
    if (m0 >= cnt) return;
    const int* __restrict__ list = g_list[e];

    extern __shared__ char smem_c[];
    const uint32_t sbA = smem_u32(smem_c);                 // [NSTAGE][64][80B]
    const uint32_t sbB = sbA + NSTAGE * A_STAGE;           // interleaved after A
    float* res = (float*)(smem_c + STG_BYTES);             // [64][RES_STRIDE]
    const float4* bias4  = (const float4*)(smem_c + SM_BIAS);
    const float4* gamma4 = (const float4*)(smem_c + SM_GAMMA);
    const float4* beta4  = (const float4*)(smem_c + SM_BETA);

    const int tid  = threadIdx.x;
    const int lane = tid & 31;
    const int wid  = tid >> 5;
    const int warp_m = wid & 3;           // 16 rows each
    const int warp_n = wid >> 2;          // 64 cols each
    const int gr = lane >> 2;
    const int tc = lane & 3;

    // params into smem
    for (int c = tid; c < DIM; c += 256) {
        ((float*)(smem_c + SM_BIAS))[c]  = Bias[e * DIM + c];
        ((float*)(smem_c + SM_GAMMA))[c] = gamma[c];
        ((float*)(smem_c + SM_BETA))[c]  = beta[c];
    }

    // ---- cp.async loaders ----
    // A: each thread 1x16B. row = tid>>2 (0..63), qo = tid&3 (16B chunk in 64B row)
    const int a_row = tid >> 2, a_q = tid & 3;
    const __half* a_g = &g_xh[e][(size_t)(m0 + a_row) * DIM + a_q * 8];
    const uint32_t dA0 = sbA + a_row * ROW_B + a_q * 16;
    // B: each thread 2x16B. row = tid>>1 (0..127), half = tid&1 (32B)
    const int b_row = tid >> 1, b_h = tid & 1;
    const __half* w_base = g_wh + (size_t)e * DIM * DIM;
    const uint32_t dB0 = sbB + b_row * ROW_B + b_h * 32;

    auto issue = [&](int ktg) {
        const int s  = ktg & (NSTAGE - 1);
        const int nb = ktg >> 4;           // n-block
        const int kt = ktg & 15;           // k-iter within block
        CP_ASYNC16(dA0 + s * A_STAGE, a_g + kt * BK);
        const __half* bg = w_base + (size_t)(nb * BN + b_row) * DIM + kt * BK + b_h * 16;
        const uint32_t dB = dB0 + s * B_STAGE;
        CP_ASYNC16(dB, bg);
        CP_ASYNC16(dB + 16, bg + 8);
    };

    // ---- ldmatrix base addresses ----
    const int lg8 = lane >> 3;
    const int lr8 = lane & 7;
    const uint32_t aLm = sbA + (warp_m * 16 + (lg8 & 1) * 8 + lr8) * ROW_B + (lg8 >> 1) * 16;
    const uint32_t bLm = sbB + (warp_n * 64 + ((lg8 >> 1) & 1) * 8 + lr8) * ROW_B + (lg8 & 1) * 16;

    issue(0); CP_COMMIT();
    issue(1); CP_COMMIT();
    issue(2); CP_COMMIT();

    int ktg = 0;
    for (int nb = 0; nb < NNB; ++nb) {
        float acc[8][4];
#pragma unroll
        for (int j = 0; j < 8; ++j)
#pragma unroll
            for (int q = 0; q < 4; ++q) acc[j][q] = 0.f;

        for (int kt = 0; kt < NKT; ++kt, ++ktg) {
            CP_WAIT2();
            __syncthreads();
            const int s = ktg & (NSTAGE - 1);
            const uint32_t aS = aLm + s * A_STAGE;
            const uint32_t bS = bLm + s * B_STAGE;
#pragma unroll
            for (int ks = 0; ks < 2; ++ks) {
                unsigned afr[4], bfr[8][2];
                LDMX4(afr[0], afr[1], afr[2], afr[3], aS + ks * 32);
#pragma unroll
                for (int j = 0; j < 4; ++j)
                    LDMX4(bfr[2 * j][0], bfr[2 * j][1], bfr[2 * j + 1][0], bfr[2 * j + 1][1],
                          bS + j * 16 * ROW_B + ks * 32);
#pragma unroll
                for (int j = 0; j < 8; ++j)
                    mma_f16(acc[j], afr, bfr[j]);
            }
            __syncthreads();
            if (ktg + 3 < NKTG) { issue(ktg + 3); }
            CP_COMMIT();
        }

        // store sub-tile to result smem (raw, no bias)
        const int r0 = warp_m * 16 + gr;
        const int cb = nb * BN + warp_n * 64;
#pragma unroll
        for (int j = 0; j < 8; ++j) {
            const int cc = cb + j * 8 + 2 * tc;
            float2 v0, v1;
            v0.x = acc[j][0]; v0.y = acc[j][1];
            v1.x = acc[j][2]; v1.y = acc[j][3];
            *(float2*)(res + r0 * RES_STRIDE + cc)       = v0;
            *(float2*)(res + (r0 + 8) * RES_STRIDE + cc) = v1;
        }
    }
    __syncthreads();

    // ---- epilogue: warp per row, 8 rows per warp ----
    for (int rr = 0; rr < 8; ++rr) {
        const int rw = wid * 8 + rr;
        const int mi = m0 + rw;
        if (mi >= cnt) break;            // warp-uniform
        const int m = list[mi];

        // pass 1: load row + bias, sum
        float4 xv[4];
        float s = 0.f;
#pragma unroll
        for (int q = 0; q < 4; ++q) {
            const int c4 = lane + q * 32;
            float4 v = *(const float4*)(res + rw * RES_STRIDE + c4 * 4);
            float4 bb = bias4[c4];
            v.x += bb.x; v.y += bb.y; v.z += bb.z; v.w += bb.w;
            xv[q] = v;
            s += v.x + v.y + v.z + v.w;
        }
#pragma unroll
        for (int o = 16; o > 0; o >>= 1) s += __shfl_xor_sync(0xffffffffu, s, o);
        const float mu = s * (1.0f / DIM);

        // pass 2: variance on register-resident deltas
        float ss = 0.f;
#pragma unroll
        for (int q = 0; q < 4; ++q) {
            xv[q].x -= mu; xv[q].y -= mu; xv[q].z -= mu; xv[q].w -= mu;
            ss += xv[q].x * xv[q].x + xv[q].y * xv[q].y
                + xv[q].z * xv[q].z + xv[q].w * xv[q].w;
        }
#pragma unroll
        for (int o = 16; o > 0; o >>= 1) ss += __shfl_xor_sync(0xffffffffu, ss, o);
        const float rstd = rsqrtf(ss * (1.0f / DIM) + LN_EPS);

        // indices for logits
        int i = m / (NB * NL);
        int rm = m - i * (NB * NL);
        int b = rm / NL;
        int l = rm - b * NL;
        int gidx = b * (ND * NL) + i * NL + l;
        const float4* pe = (const float4*)(emb + (size_t)pos_idx[gidx] * DIM);
        const float4* ne = (const float4*)(emb + (size_t)neg_idx[gidx] * DIM);
        float4* yd = (float4*)(Y + (size_t)m * DIM);

        float dp = 0.f, dn = 0.f;
#pragma unroll
        for (int q = 0; q < 4; ++q) {
            const int c4 = lane + q * 32;
            float4 g = gamma4[c4], be = beta4[c4];
            float4 y;
            y.x = xv[q].x * rstd * g.x + be.x;
            y.y = xv[q].y * rstd * g.y + be.y;
            y.z = xv[q].z * rstd * g.z + be.z;
            y.w = xv[q].w * rstd * g.w + be.w;
            yd[c4] = y;
            float4 p = pe[c4], n = ne[c4];
            dp += y.x * p.x + y.y * p.y + y.z * p.z + y.w * p.w;
            dn += y.x * n.x + y.y * n.y + y.z * n.z + y.w * n.w;
        }
#pragma unroll
        for (int o = 16; o > 0; o >>= 1) {
            dp += __shfl_xor_sync(0xffffffffu, dp, o);
            dn += __shfl_xor_sync(0xffffffffu, dn, o);
        }
        if (lane == 0) {
            pos_out[m] = dp;
            neg_out[m] = dn;
        }
    }
}

// ================= kernel 4: pad tokens (lg==0) =================
__global__ void __launch_bounds__(256)
pad_kernel(float* __restrict__ Y, float* __restrict__ pos_out, float* __restrict__ neg_out,
           const float* __restrict__ emb, const float* __restrict__ beta,
           const int* __restrict__ pos_idx, const int* __restrict__ neg_idx)
{
    const int np   = g_count[4];
    const int gw   = (blockIdx.x * blockDim.x + threadIdx.x) >> 5;
    const int lane = threadIdx.x & 31;
    const int nw   = (gridDim.x * blockDim.x) >> 5;
    const float4* bt = (const float4*)beta;

    for (int t = gw; t < np; t += nw) {
        int m = g_list[4][t];
        int i = m / (NB * NL);
        int rr = m - i * (NB * NL);
        int b = rr / NL;
        int l = rr - b * NL;
        int gidx = b * (ND * NL) + i * NL + l;
        const float4* pe = (const float4*)(emb + (size_t)pos_idx[gidx] * DIM);
        const float4* ne = (const float4*)(emb + (size_t)neg_idx[gidx] * DIM);
        float4* yd = (float4*)(Y + (size_t)m * DIM);
        float dp = 0.f, dn = 0.f;
        for (int c = lane; c < DIM / 4; c += 32) {
            float4 bv = bt[c];
            yd[c] = bv;
            float4 p = pe[c];
            float4 n = ne[c];
            dp += bv.x * p.x + bv.y * p.y + bv.z * p.z + bv.w * p.w;
            dn += bv.x * n.x + bv.y * n.y + bv.z * n.z + bv.w * n.w;
        }
#pragma unroll
        for (int o = 16; o > 0; o >>= 1) {
            dp += __shfl_xor_sync(0xffffffffu, dp, o);
            dn += __shfl_xor_sync(0xffffffffu, dn, o);
        }
        if (lane == 0) {
            pos_out[m] = dp;
            neg_out[m] = dn;
        }
    }
}

// ================= launch =================
extern "C" void kernel_launch(void* const* d_in, const int* in_sizes, int n_in,
                              void* d_out, int out_size) {
    const float* X     = (const float*)d_in[0];   // log_feats [4,128,200,512]
    const float* Wm    = (const float*)d_in[1];   // W_maps [4,512,512]
    const float* bm    = (const float*)d_in[2];   // b_maps [4,512]
    const float* emb   = (const float*)d_in[3];   // emb_table [100002,512]
    const float* gamma = (const float*)d_in[4];   // [512]
    const float* beta  = (const float*)d_in[5];   // [512]
    const int*   lg    = (const int*)d_in[6];     // lg_dom [128,4,200]
    const int*   pos   = (const int*)d_in[7];     // pos_oth_dom [128,4,200]
    const int*   neg   = (const int*)d_in[8];     // neg_oth_dom [128,4,200]

    float* out     = (float*)d_out;
    float* mapped  = out;
    float* pos_out = out + (size_t)M_TOTAL * DIM;
    float* neg_out = pos_out + M_TOTAL;

    static bool attr_set = false;
    if (!attr_set) {
        cudaFuncSetAttribute(fused_kernel,
                             cudaFuncAttributeMaxDynamicSharedMemorySize,
                             SMEM_BYTES);
        attr_set = true;
    }

    reset_kernel<<<1, 32>>>();
    route_kernel<<<(M_TOTAL + 255) / 256, 256>>>(lg);

    wconv_kernel<<<(ND * DIM * DIM / 8) / 256, 256>>>(Wm);
    {
        dim3 g((CAP * 64) / 256, ND);
        xconv_kernel<<<g, 256>>>(X);
    }

    dim3 grid(MBLK, ND);
    fused_kernel<<<grid, 256, SMEM_BYTES>>>(bm, emb, gamma, beta, pos, neg,
                                            mapped, pos_out, neg_out);

    pad_kernel<<<256, 256>>>(mapped, pos_out, neg_out, emb, beta, pos, neg);
}

// round 9
// speedup vs baseline: 1.2979x; 1.2979x over previous
#include <cuda_runtime.h>
#include <cuda_fp16.h>
#include <cstdint>
#include <cstddef>

#define ND 4
#define NB 128
#define NL 200
#define DIM 512
#define M_TOTAL (ND * NB * NL)   // 102400
#define LN_EPS 1e-8f

// GEMM tiling (R7 shape — do not shrink)
#define BM 128
#define BN 128
#define BK 32
#define NKT (DIM / BK)           // 16
#define NNB (DIM / BN)           // 4 n-blocks per m-block
#define ROW_B 80                 // padded row stride in bytes
#define STAGE_B (BM * ROW_B)     // 10240
#define NSTAGE 4
#define SMEM_BYTES (2 * NSTAGE * STAGE_B)   // 81920

// per-expert capacity (mean cnt ~20480, sd ~128)
#define CAP 24576
#define MBLK (CAP / BM)          // 192

// -------- device scratch (static, allocation-guard-safe) --------
__device__ int g_count[5];               // 4 experts + pad bucket
__device__ int g_list[5][M_TOTAL];
__device__ int g_arrive[ND][MBLK];
__device__ __half g_xh[ND][(size_t)CAP * DIM];   // 96 MB compacted fp16 X
__device__ __half g_wh[ND * DIM * DIM];          // 2 MB fp16 W

// -------- helpers --------
__device__ __forceinline__ unsigned pack_h2(float lo, float hi) {
    unsigned d;
    asm("cvt.rn.f16x2.f32 %0, %1, %2;" : "=r"(d) : "f"(hi), "f"(lo));
    return d;
}
__device__ __forceinline__ uint32_t smem_u32(const void* p) {
    uint32_t a;
    asm("{ .reg .u64 t; cvta.to.shared.u64 t, %1; cvt.u32.u64 %0, t; }" : "=r"(a) : "l"(p));
    return a;
}
#define CP_ASYNC16(dst, src) \
    asm volatile("cp.async.cg.shared.global [%0], [%1], 16;" :: "r"(dst), "l"(src) : "memory")
#define CP_COMMIT() asm volatile("cp.async.commit_group;" ::: "memory")
#define CP_WAIT2()  asm volatile("cp.async.wait_group 2;" ::: "memory")

#define LDMX4(r0, r1, r2, r3, a) \
    asm volatile("ldmatrix.sync.aligned.m8n8.x4.shared.b16 {%0,%1,%2,%3}, [%4];" \
        : "=r"(r0), "=r"(r1), "=r"(r2), "=r"(r3) : "r"(a))

__device__ __forceinline__ void mma_f16(float* d, const unsigned* a, const unsigned* b) {
    asm("mma.sync.aligned.m16n8k16.row.col.f32.f16.f16.f32 "
        "{%0,%1,%2,%3}, {%4,%5,%6,%7}, {%8,%9}, {%0,%1,%2,%3};"
        : "+f"(d[0]), "+f"(d[1]), "+f"(d[2]), "+f"(d[3])
        : "r"(a[0]), "r"(a[1]), "r"(a[2]), "r"(a[3]),
          "r"(b[0]), "r"(b[1]));
}

// ================= kernel 0: reset counters + arrival flags =================
__global__ void reset_kernel() {
    int t = threadIdx.x;
    if (t < 5) g_count[t] = 0;
    for (int i = t; i < ND * MBLK; i += blockDim.x)
        ((int*)g_arrive)[i] = 0;
}

// ================= kernel 1: routing (experts + pad bucket) =================
__global__ void route_kernel(const int* __restrict__ lg_dom) {
    int m = blockIdx.x * blockDim.x + threadIdx.x;
    if (m >= M_TOTAL) return;
    int i = m / (NB * NL);
    int r = m - i * (NB * NL);
    int b = r / NL;
    int l = r - b * NL;
    int lg = lg_dom[b * (ND * NL) + i * NL + l];
    int bucket = (lg > 0) ? (lg - 1) : 4;
    int slot = atomicAdd(&g_count[bucket], 1);
    g_list[bucket][slot] = m;
}

// ================= kernel 2a: convert W -> fp16 =================
__global__ void wconv_kernel(const float* __restrict__ W) {
    int t = blockIdx.x * blockDim.x + threadIdx.x;   // 8 floats each
    const float4 v0 = ((const float4*)W)[t * 2];
    const float4 v1 = ((const float4*)W)[t * 2 + 1];
    uint4 o;
    o.x = pack_h2(v0.x, v0.y);
    o.y = pack_h2(v0.z, v0.w);
    o.z = pack_h2(v1.x, v1.y);
    o.w = pack_h2(v1.z, v1.w);
    ((uint4*)g_wh)[t] = o;
}

// ================= kernel 2b: gather + compact + convert X -> fp16 =================
__global__ void xconv_kernel(const float* __restrict__ X) {
    const int e = blockIdx.y;
    const int cnt = g_count[e];
    const int rcap = (cnt + BM - 1) & ~(BM - 1);
    const int t = blockIdx.x * blockDim.x + threadIdx.x;  // r * 64 + c
    const int r = t >> 6;
    if (r >= rcap) return;
    const int c = t & 63;
    uint4 o;
    if (r < cnt) {
        const float4* src = (const float4*)(X + (size_t)g_list[e][r] * DIM + c * 8);
        float4 v0 = src[0], v1 = src[1];
        o.x = pack_h2(v0.x, v0.y);
        o.y = pack_h2(v0.z, v0.w);
        o.z = pack_h2(v1.x, v1.y);
        o.w = pack_h2(v1.z, v1.w);
    } else {
        o = make_uint4(0u, 0u, 0u, 0u);
    }
    *(uint4*)(&g_xh[e][(size_t)r * DIM + c * 8]) = o;
}

// ================= kernel 3: GEMM + cross-CTA LN/logits epilogue =================
// R7 GEMM (128x128, cp.async 4-stage, ldmatrix, mma m16n8k16). After the
// bias+scatter store, CTAs arrive on a per-(e,mblk) counter; the last of the
// 4 n-block CTAs re-reads the 128 completed rows from L2 (ldcg) and performs
// LN + Y overwrite + pos/neg logit dots.
__global__ void __launch_bounds__(256, 2)
gemm_fused_kernel(const float* __restrict__ Bias, const float* __restrict__ emb,
                  const float* __restrict__ gamma, const float* __restrict__ beta,
                  const int* __restrict__ pos_idx, const int* __restrict__ neg_idx,
                  float* __restrict__ Y, float* __restrict__ pos_out,
                  float* __restrict__ neg_out)
{
    const int e   = blockIdx.z;
    const int cnt = g_count[e];
    const int mb  = blockIdx.y;
    const int m0  = mb * BM;
    if (m0 >= cnt) return;
    const int n0 = blockIdx.x * BN;
    const int* __restrict__ list = g_list[e];

    extern __shared__ char smem_c[];
    const uint32_t sbA = smem_u32(smem_c);
    const uint32_t sbB = sbA + NSTAGE * STAGE_B;

    const int tid  = threadIdx.x;
    const int lane = tid & 31;
    const int wid  = tid >> 5;
    const int warp_m = wid & 3;
    const int warp_n = wid >> 2;
    const int gr = lane >> 2;
    const int tc = lane & 3;

    // ---- cp.async loaders: 2 threads per row, 2 x 16B each ----
    const int l_row  = tid >> 1;
    const int l_half = tid & 1;
    const __half* a_g = &g_xh[e][(size_t)(m0 + l_row) * DIM + l_half * 16];
    const __half* b_g = g_wh + (size_t)e * DIM * DIM + (size_t)(n0 + l_row) * DIM + l_half * 16;
    const uint32_t dA0 = sbA + l_row * ROW_B + l_half * 32;
    const uint32_t dB0 = sbB + l_row * ROW_B + l_half * 32;

    auto issue = [&](int kt) {
        const int s = kt % NSTAGE;
        const int k0 = kt * BK;
        const uint32_t dA = dA0 + s * STAGE_B;
        const uint32_t dB = dB0 + s * STAGE_B;
        CP_ASYNC16(dA, a_g + k0);
        CP_ASYNC16(dA + 16, a_g + k0 + 8);
        CP_ASYNC16(dB, b_g + k0);
        CP_ASYNC16(dB + 16, b_g + k0 + 8);
    };

    const int lg8 = lane >> 3;
    const int lr8 = lane & 7;
    const uint32_t aLm = sbA + (warp_m * 32 + (lg8 & 1) * 8 + lr8) * ROW_B + (lg8 >> 1) * 16;
    const uint32_t bLm = sbB + (warp_n * 64 + ((lg8 >> 1) & 1) * 8 + lr8) * ROW_B + (lg8 & 1) * 16;

    float acc[2][8][4];
#pragma unroll
    for (int i = 0; i < 2; ++i)
#pragma unroll
        for (int j = 0; j < 8; ++j)
#pragma unroll
            for (int q = 0; q < 4; ++q) acc[i][j][q] = 0.f;

    issue(0); CP_COMMIT();
    issue(1); CP_COMMIT();
    issue(2); CP_COMMIT();

    for (int kt = 0; kt < NKT; ++kt) {
        CP_WAIT2();
        __syncthreads();
        const int s = kt % NSTAGE;
        const uint32_t aS = aLm + s * STAGE_B;
        const uint32_t bS = bLm + s * STAGE_B;
#pragma unroll
        for (int ks = 0; ks < 2; ++ks) {
            unsigned afr[2][4], bfr[8][2];
#pragma unroll
            for (int i = 0; i < 2; ++i)
                LDMX4(afr[i][0], afr[i][1], afr[i][2], afr[i][3],
                      aS + i * 16 * ROW_B + ks * 32);
#pragma unroll
            for (int j = 0; j < 4; ++j)
                LDMX4(bfr[2 * j][0], bfr[2 * j][1], bfr[2 * j + 1][0], bfr[2 * j + 1][1],
                      bS + j * 16 * ROW_B + ks * 32);
#pragma unroll
            for (int i = 0; i < 2; ++i)
#pragma unroll
                for (int j = 0; j < 8; ++j)
                    mma_f16(acc[i][j], afr[i], bfr[j]);
        }
        __syncthreads();
        if (kt + 3 < NKT) issue(kt + 3);
        CP_COMMIT();
    }

    // ---- epilogue: bias add + scatter to gathered rows ----
#pragma unroll
    for (int i = 0; i < 2; ++i) {
        const int mr0 = m0 + warp_m * 32 + i * 16 + gr;
        const int mr1 = mr0 + 8;
        const bool v0 = (mr0 < cnt);
        const bool v1 = (mr1 < cnt);
        float* dst0 = v0 ? (Y + (size_t)list[mr0] * DIM + n0) : nullptr;
        float* dst1 = v1 ? (Y + (size_t)list[mr1] * DIM + n0) : nullptr;
#pragma unroll
        for (int j = 0; j < 8; ++j) {
            const int nf = warp_n * 64 + j * 8 + 2 * tc;
            float2 bv = *(const float2*)(Bias + e * DIM + n0 + nf);
            if (v0) {
                float2 o;
                o.x = acc[i][j][0] + bv.x;
                o.y = acc[i][j][1] + bv.y;
                *(float2*)(dst0 + nf) = o;
            }
            if (v1) {
                float2 o;
                o.x = acc[i][j][2] + bv.x;
                o.y = acc[i][j][3] + bv.y;
                *(float2*)(dst1 + nf) = o;
            }
        }
    }

    // ---- cross-CTA arrival: last n-block CTA runs LN + logits ----
    __threadfence();
    __shared__ int s_last;
    __syncthreads();
    if (tid == 0) {
        int old = atomicAdd(&g_arrive[e][mb], 1);
        s_last = (old == NNB - 1) ? 1 : 0;
    }
    __syncthreads();
    if (!s_last) return;
    __threadfence();   // acquire side

    // 8 warps x 16 rows = 128 rows
    for (int rr = 0; rr < 16; ++rr) {
        const int rw = wid * 16 + rr;
        const int mi = m0 + rw;
        if (mi >= cnt) break;          // warp-uniform
        const int m = list[mi];
        float* yrow = Y + (size_t)m * DIM;

        // pass 1: load full row via L2 (ldcg), sum
        float4 xv[4];
        float s = 0.f;
#pragma unroll
        for (int q = 0; q < 4; ++q) {
            const int c4 = lane + q * 32;
            float4 v = __ldcg((const float4*)(yrow + c4 * 4));
            xv[q] = v;
            s += v.x + v.y + v.z + v.w;
        }
#pragma unroll
        for (int o = 16; o > 0; o >>= 1) s += __shfl_xor_sync(0xffffffffu, s, o);
        const float mu = s * (1.0f / DIM);

        float ss = 0.f;
#pragma unroll
        for (int q = 0; q < 4; ++q) {
            xv[q].x -= mu; xv[q].y -= mu; xv[q].z -= mu; xv[q].w -= mu;
            ss += xv[q].x * xv[q].x + xv[q].y * xv[q].y
                + xv[q].z * xv[q].z + xv[q].w * xv[q].w;
        }
#pragma unroll
        for (int o = 16; o > 0; o >>= 1) ss += __shfl_xor_sync(0xffffffffu, ss, o);
        const float rstd = rsqrtf(ss * (1.0f / DIM) + LN_EPS);

        int i = m / (NB * NL);
        int rm = m - i * (NB * NL);
        int b = rm / NL;
        int l = rm - b * NL;
        int gidx = b * (ND * NL) + i * NL + l;
        const float4* pe = (const float4*)(emb + (size_t)pos_idx[gidx] * DIM);
        const float4* ne = (const float4*)(emb + (size_t)neg_idx[gidx] * DIM);

        float dp = 0.f, dn = 0.f;
#pragma unroll
        for (int q = 0; q < 4; ++q) {
            const int c4 = lane + q * 32;
            float4 g = __ldg((const float4*)gamma + c4);
            float4 be = __ldg((const float4*)beta + c4);
            float4 y;
            y.x = xv[q].x * rstd * g.x + be.x;
            y.y = xv[q].y * rstd * g.y + be.y;
            y.z = xv[q].z * rstd * g.z + be.z;
            y.w = xv[q].w * rstd * g.w + be.w;
            *(float4*)(yrow + c4 * 4) = y;
            float4 p = pe[c4], n = ne[c4];
            dp += y.x * p.x + y.y * p.y + y.z * p.z + y.w * p.w;
            dn += y.x * n.x + y.y * n.y + y.z * n.z + y.w * n.w;
        }
#pragma unroll
        for (int o = 16; o > 0; o >>= 1) {
            dp += __shfl_xor_sync(0xffffffffu, dp, o);
            dn += __shfl_xor_sync(0xffffffffu, dn, o);
        }
        if (lane == 0) {
            pos_out[m] = dp;
            neg_out[m] = dn;
        }
    }
}

// ================= kernel 4: pad tokens (lg==0) =================
__global__ void __launch_bounds__(256)
pad_kernel(float* __restrict__ Y, float* __restrict__ pos_out, float* __restrict__ neg_out,
           const float* __restrict__ emb, const float* __restrict__ beta,
           const int* __restrict__ pos_idx, const int* __restrict__ neg_idx)
{
    const int np   = g_count[4];
    const int gw   = (blockIdx.x * blockDim.x + threadIdx.x) >> 5;
    const int lane = threadIdx.x & 31;
    const int nw   = (gridDim.x * blockDim.x) >> 5;
    const float4* bt = (const float4*)beta;

    for (int t = gw; t < np; t += nw) {
        int m = g_list[4][t];
        int i = m / (NB * NL);
        int rr = m - i * (NB * NL);
        int b = rr / NL;
        int l = rr - b * NL;
        int gidx = b * (ND * NL) + i * NL + l;
        const float4* pe = (const float4*)(emb + (size_t)pos_idx[gidx] * DIM);
        const float4* ne = (const float4*)(emb + (size_t)neg_idx[gidx] * DIM);
        float4* yd = (float4*)(Y + (size_t)m * DIM);
        float dp = 0.f, dn = 0.f;
        for (int c = lane; c < DIM / 4; c += 32) {
            float4 bv = bt[c];
            yd[c] = bv;
            float4 p = pe[c];
            float4 n = ne[c];
            dp += bv.x * p.x + bv.y * p.y + bv.z * p.z + bv.w * p.w;
            dn += bv.x * n.x + bv.y * n.y + bv.z * n.z + bv.w * n.w;
        }
#pragma unroll
        for (int o = 16; o > 0; o >>= 1) {
            dp += __shfl_xor_sync(0xffffffffu, dp, o);
            dn += __shfl_xor_sync(0xffffffffu, dn, o);
        }
        if (lane == 0) {
            pos_out[m] = dp;
            neg_out[m] = dn;
        }
    }
}

// ================= launch =================
extern "C" void kernel_launch(void* const* d_in, const int* in_sizes, int n_in,
                              void* d_out, int out_size) {
    const float* X     = (const float*)d_in[0];   // log_feats [4,128,200,512]
    const float* Wm    = (const float*)d_in[1];   // W_maps [4,512,512]
    const float* bm    = (const float*)d_in[2];   // b_maps [4,512]
    const float* emb   = (const float*)d_in[3];   // emb_table [100002,512]
    const float* gamma = (const float*)d_in[4];   // [512]
    const float* beta  = (const float*)d_in[5];   // [512]
    const int*   lg    = (const int*)d_in[6];     // lg_dom [128,4,200]
    const int*   pos   = (const int*)d_in[7];     // pos_oth_dom [128,4,200]
    const int*   neg   = (const int*)d_in[8];     // neg_oth_dom [128,4,200]

    float* out     = (float*)d_out;
    float* mapped  = out;
    float* pos_out = out + (size_t)M_TOTAL * DIM;
    float* neg_out = pos_out + M_TOTAL;

    static bool attr_set = false;
    if (!attr_set) {
        cudaFuncSetAttribute(gemm_fused_kernel,
                             cudaFuncAttributeMaxDynamicSharedMemorySize,
                             SMEM_BYTES);
        attr_set = true;
    }

    reset_kernel<<<1, 1024>>>();
    route_kernel<<<(M_TOTAL + 255) / 256, 256>>>(lg);

    wconv_kernel<<<(ND * DIM * DIM / 8) / 256, 256>>>(Wm);
    {
        dim3 g((CAP * 64) / 256, ND);
        xconv_kernel<<<g, 256>>>(X);
    }

    dim3 grid(DIM / BN, MBLK, ND);
    gemm_fused_kernel<<<grid, 256, SMEM_BYTES>>>(bm, emb, gamma, beta, pos, neg,
                                                 mapped, pos_out, neg_out);

    pad_kernel<<<256, 256>>>(mapped, pos_out, neg_out, emb, beta, pos, neg);
}

// round 11
// speedup vs baseline: 1.4282x; 1.1004x over previous
#include <cuda_runtime.h>
#include <cuda_fp16.h>
#include <cstdint>
#include <cstddef>

#define ND 4
#define NB 128
#define NL 200
#define DIM 512
#define M_TOTAL (ND * NB * NL)   // 102400
#define LN_EPS 1e-8f

// GEMM tiling (R7 shape — do not shrink)
#define BM 128
#define BN 128
#define BK 32
#define NKT (DIM / BK)           // 16
#define NNB (DIM / BN)           // 4 n-blocks per m-block
#define ROW_B 80                 // padded row stride in bytes
#define STAGE_B (BM * ROW_B)     // 10240
#define NSTAGE 4
#define SMEM_BYTES (2 * NSTAGE * STAGE_B)   // 81920

// per-expert capacity (mean cnt ~20480, sd ~128)
#define CAP 24576
#define MBLK (CAP / BM)          // 192

// -------- device scratch (static, allocation-guard-safe) --------
__device__ int g_count[5];               // 4 experts + pad bucket
__device__ int g_list[5][M_TOTAL];
__device__ int g_arrive[ND][MBLK];
__device__ __half g_xh[ND][(size_t)CAP * DIM];   // 96 MB compacted fp16 X
__device__ __half g_wh[ND * DIM * DIM];          // 2 MB fp16 W

// -------- helpers --------
__device__ __forceinline__ unsigned pack_h2(float lo, float hi) {
    unsigned d;
    asm("cvt.rn.f16x2.f32 %0, %1, %2;" : "=r"(d) : "f"(hi), "f"(lo));
    return d;
}
__device__ __forceinline__ uint32_t smem_u32(const void* p) {
    uint32_t a;
    asm("{ .reg .u64 t; cvta.to.shared.u64 t, %1; cvt.u32.u64 %0, t; }" : "=r"(a) : "l"(p));
    return a;
}
#define CP_ASYNC16(dst, src) \
    asm volatile("cp.async.cg.shared.global [%0], [%1], 16;" :: "r"(dst), "l"(src) : "memory")
#define CP_COMMIT() asm volatile("cp.async.commit_group;" ::: "memory")
#define CP_WAIT2()  asm volatile("cp.async.wait_group 2;" ::: "memory")

#define LDMX4(r0, r1, r2, r3, a) \
    asm volatile("ldmatrix.sync.aligned.m8n8.x4.shared.b16 {%0,%1,%2,%3}, [%4];" \
        : "=r"(r0), "=r"(r1), "=r"(r2), "=r"(r3) : "r"(a))

__device__ __forceinline__ void mma_f16(float* d, const unsigned* a, const unsigned* b) {
    asm("mma.sync.aligned.m16n8k16.row.col.f32.f16.f16.f32 "
        "{%0,%1,%2,%3}, {%4,%5,%6,%7}, {%8,%9}, {%0,%1,%2,%3};"
        : "+f"(d[0]), "+f"(d[1]), "+f"(d[2]), "+f"(d[3])
        : "r"(a[0]), "r"(a[1]), "r"(a[2]), "r"(a[3]),
          "r"(b[0]), "r"(b[1]));
}

// ================= kernel 0: reset counters + arrival flags =================
__global__ void reset_kernel() {
    int t = threadIdx.x;
    if (t < 5) g_count[t] = 0;
    for (int i = t; i < ND * MBLK; i += blockDim.x)
        ((int*)g_arrive)[i] = 0;
}

// ================= kernel 1: routing (experts + pad bucket) =================
__global__ void route_kernel(const int* __restrict__ lg_dom) {
    int m = blockIdx.x * blockDim.x + threadIdx.x;
    if (m >= M_TOTAL) return;
    int i = m / (NB * NL);
    int r = m - i * (NB * NL);
    int b = r / NL;
    int l = r - b * NL;
    int lg = lg_dom[b * (ND * NL) + i * NL + l];
    int bucket = (lg > 0) ? (lg - 1) : 4;
    int slot = atomicAdd(&g_count[bucket], 1);
    g_list[bucket][slot] = m;
}

// ================= kernel 2a: convert W -> fp16 =================
__global__ void wconv_kernel(const float* __restrict__ W) {
    int t = blockIdx.x * blockDim.x + threadIdx.x;   // 8 floats each
    const float4 v0 = ((const float4*)W)[t * 2];
    const float4 v1 = ((const float4*)W)[t * 2 + 1];
    uint4 o;
    o.x = pack_h2(v0.x, v0.y);
    o.y = pack_h2(v0.z, v0.w);
    o.z = pack_h2(v1.x, v1.y);
    o.w = pack_h2(v1.z, v1.w);
    ((uint4*)g_wh)[t] = o;
}

// ================= kernel 2b: gather + compact + convert X -> fp16 =================
__global__ void xconv_kernel(const float* __restrict__ X) {
    const int e = blockIdx.y;
    const int cnt = g_count[e];
    const int rcap = (cnt + BM - 1) & ~(BM - 1);
    const int t = blockIdx.x * blockDim.x + threadIdx.x;  // r * 64 + c
    const int r = t >> 6;
    if (r >= rcap) return;
    const int c = t & 63;
    uint4 o;
    if (r < cnt) {
        const float4* src = (const float4*)(X + (size_t)g_list[e][r] * DIM + c * 8);
        float4 v0 = src[0], v1 = src[1];
        o.x = pack_h2(v0.x, v0.y);
        o.y = pack_h2(v0.z, v0.w);
        o.z = pack_h2(v1.x, v1.y);
        o.w = pack_h2(v1.z, v1.w);
    } else {
        o = make_uint4(0u, 0u, 0u, 0u);
    }
    *(uint4*)(&g_xh[e][(size_t)r * DIM + c * 8]) = o;
}

// ================= kernel 3: GEMM + cross-CTA LN/logits + pad slice =================
// grid (NNB, MBLK, ND+1). z<ND: R7-shape GEMM with cross-CTA LN epilogue.
// z==ND, x==0: pad-token slice (mapped=beta, logits=beta.emb) — memory-bound
// CTAs interleaved into the same wave as the tensor-bound GEMM CTAs.
__global__ void __launch_bounds__(256, 2)
gemm_fused_kernel(const float* __restrict__ Bias, const float* __restrict__ emb,
                  const float* __restrict__ gamma, const float* __restrict__ beta,
                  const int* __restrict__ pos_idx, const int* __restrict__ neg_idx,
                  float* __restrict__ Y, float* __restrict__ pos_out,
                  float* __restrict__ neg_out)
{
    const int e   = blockIdx.z;
    const int mb  = blockIdx.y;
    const int tid  = threadIdx.x;
    const int lane = tid & 31;
    const int wid  = tid >> 5;

    // ---------------- pad-token slice ----------------
    if (e == ND) {
        if (blockIdx.x != 0) return;
        const int np = g_count[4];
        const int t0 = mb * BM;
        if (t0 >= np) return;
        for (int rr = 0; rr < 16; ++rr) {
            const int ti = t0 + wid * 16 + rr;
            if (ti >= np) break;          // warp-uniform
            int m = g_list[4][ti];
            int i = m / (NB * NL);
            int rm = m - i * (NB * NL);
            int b = rm / NL;
            int l = rm - b * NL;
            int gidx = b * (ND * NL) + i * NL + l;
            const float4* pe = (const float4*)(emb + (size_t)pos_idx[gidx] * DIM);
            const float4* ne = (const float4*)(emb + (size_t)neg_idx[gidx] * DIM);
            float4* yd = (float4*)(Y + (size_t)m * DIM);
            float dp = 0.f, dn = 0.f;
#pragma unroll
            for (int q = 0; q < 4; ++q) {
                const int c4 = lane + q * 32;
                float4 bv = __ldg((const float4*)beta + c4);
                yd[c4] = bv;
                float4 p = pe[c4], n = ne[c4];
                dp += bv.x * p.x + bv.y * p.y + bv.z * p.z + bv.w * p.w;
                dn += bv.x * n.x + bv.y * n.y + bv.z * n.z + bv.w * n.w;
            }
#pragma unroll
            for (int o = 16; o > 0; o >>= 1) {
                dp += __shfl_xor_sync(0xffffffffu, dp, o);
                dn += __shfl_xor_sync(0xffffffffu, dn, o);
            }
            if (lane == 0) {
                pos_out[m] = dp;
                neg_out[m] = dn;
            }
        }
        return;
    }

    // ---------------- GEMM path ----------------
    const int cnt = g_count[e];
    const int m0  = mb * BM;
    if (m0 >= cnt) return;
    const int n0 = blockIdx.x * BN;
    const int* __restrict__ list = g_list[e];

    extern __shared__ char smem_c[];
    const uint32_t sbA = smem_u32(smem_c);
    const uint32_t sbB = sbA + NSTAGE * STAGE_B;

    const int warp_m = wid & 3;
    const int warp_n = wid >> 2;
    const int gr = lane >> 2;
    const int tc = lane & 3;

    // ---- cp.async loaders: 2 threads per row, 2 x 16B each ----
    const int l_row  = tid >> 1;
    const int l_half = tid & 1;
    const __half* a_g = &g_xh[e][(size_t)(m0 + l_row) * DIM + l_half * 16];
    const __half* b_g = g_wh + (size_t)e * DIM * DIM + (size_t)(n0 + l_row) * DIM + l_half * 16;
    const uint32_t dA0 = sbA + l_row * ROW_B + l_half * 32;
    const uint32_t dB0 = sbB + l_row * ROW_B + l_half * 32;

    auto issue = [&](int kt) {
        const int s = kt % NSTAGE;
        const int k0 = kt * BK;
        const uint32_t dA = dA0 + s * STAGE_B;
        const uint32_t dB = dB0 + s * STAGE_B;
        CP_ASYNC16(dA, a_g + k0);
        CP_ASYNC16(dA + 16, a_g + k0 + 8);
        CP_ASYNC16(dB, b_g + k0);
        CP_ASYNC16(dB + 16, b_g + k0 + 8);
    };

    const int lg8 = lane >> 3;
    const int lr8 = lane & 7;
    const uint32_t aLm = sbA + (warp_m * 32 + (lg8 & 1) * 8 + lr8) * ROW_B + (lg8 >> 1) * 16;
    const uint32_t bLm = sbB + (warp_n * 64 + ((lg8 >> 1) & 1) * 8 + lr8) * ROW_B + (lg8 & 1) * 16;

    float acc[2][8][4];
#pragma unroll
    for (int i = 0; i < 2; ++i)
#pragma unroll
        for (int j = 0; j < 8; ++j)
#pragma unroll
            for (int q = 0; q < 4; ++q) acc[i][j][q] = 0.f;

    issue(0); CP_COMMIT();
    issue(1); CP_COMMIT();
    issue(2); CP_COMMIT();

    // single-barrier k-loop: the sync after wait_group also proves the slot
    // issue(kt+3) overwrites (stage kt-1, read in iter kt-1) is drained.
    for (int kt = 0; kt < NKT; ++kt) {
        CP_WAIT2();
        __syncthreads();
        if (kt + 3 < NKT) issue(kt + 3);
        CP_COMMIT();
        const int s = kt % NSTAGE;
        const uint32_t aS = aLm + s * STAGE_B;
        const uint32_t bS = bLm + s * STAGE_B;
#pragma unroll
        for (int ks = 0; ks < 2; ++ks) {
            unsigned afr[2][4], bfr[8][2];
#pragma unroll
            for (int i = 0; i < 2; ++i)
                LDMX4(afr[i][0], afr[i][1], afr[i][2], afr[i][3],
                      aS + i * 16 * ROW_B + ks * 32);
#pragma unroll
            for (int j = 0; j < 4; ++j)
                LDMX4(bfr[2 * j][0], bfr[2 * j][1], bfr[2 * j + 1][0], bfr[2 * j + 1][1],
                      bS + j * 16 * ROW_B + ks * 32);
#pragma unroll
            for (int i = 0; i < 2; ++i)
#pragma unroll
                for (int j = 0; j < 8; ++j)
                    mma_f16(acc[i][j], afr[i], bfr[j]);
        }
    }

    // ---- epilogue: bias add + scatter to gathered rows ----
#pragma unroll
    for (int i = 0; i < 2; ++i) {
        const int mr0 = m0 + warp_m * 32 + i * 16 + gr;
        const int mr1 = mr0 + 8;
        const bool v0 = (mr0 < cnt);
        const bool v1 = (mr1 < cnt);
        float* dst0 = v0 ? (Y + (size_t)list[mr0] * DIM + n0) : nullptr;
        float* dst1 = v1 ? (Y + (size_t)list[mr1] * DIM + n0) : nullptr;
#pragma unroll
        for (int j = 0; j < 8; ++j) {
            const int nf = warp_n * 64 + j * 8 + 2 * tc;
            float2 bv = *(const float2*)(Bias + e * DIM + n0 + nf);
            if (v0) {
                float2 o;
                o.x = acc[i][j][0] + bv.x;
                o.y = acc[i][j][1] + bv.y;
                *(float2*)(dst0 + nf) = o;
            }
            if (v1) {
                float2 o;
                o.x = acc[i][j][2] + bv.x;
                o.y = acc[i][j][3] + bv.y;
                *(float2*)(dst1 + nf) = o;
            }
        }
    }

    // ---- cross-CTA arrival: last n-block CTA runs LN + logits ----
    __threadfence();
    __shared__ int s_last;
    __syncthreads();
    if (tid == 0) {
        int old = atomicAdd(&g_arrive[e][mb], 1);
        s_last = (old == NNB - 1) ? 1 : 0;
    }
    __syncthreads();
    if (!s_last) return;
    __threadfence();   // acquire side

    // 8 warps x 16 rows = 128 rows
    for (int rr = 0; rr < 16; ++rr) {
        const int rw = wid * 16 + rr;
        const int mi = m0 + rw;
        if (mi >= cnt) break;          // warp-uniform
        const int m = list[mi];
        float* yrow = Y + (size_t)m * DIM;

        // pass 1: load full row via L2 (ldcg), sum
        float4 xv[4];
        float s = 0.f;
#pragma unroll
        for (int q = 0; q < 4; ++q) {
            const int c4 = lane + q * 32;
            float4 v = __ldcg((const float4*)(yrow + c4 * 4));
            xv[q] = v;
            s += v.x + v.y + v.z + v.w;
        }
#pragma unroll
        for (int o = 16; o > 0; o >>= 1) s += __shfl_xor_sync(0xffffffffu, s, o);
        const float mu = s * (1.0f / DIM);

        float ss = 0.f;
#pragma unroll
        for (int q = 0; q < 4; ++q) {
            xv[q].x -= mu; xv[q].y -= mu; xv[q].z -= mu; xv[q].w -= mu;
            ss += xv[q].x * xv[q].x + xv[q].y * xv[q].y
                + xv[q].z * xv[q].z + xv[q].w * xv[q].w;
        }
#pragma unroll
        for (int o = 16; o > 0; o >>= 1) ss += __shfl_xor_sync(0xffffffffu, ss, o);
        const float rstd = rsqrtf(ss * (1.0f / DIM) + LN_EPS);

        int i = m / (NB * NL);
        int rm = m - i * (NB * NL);
        int b = rm / NL;
        int l = rm - b * NL;
        int gidx = b * (ND * NL) + i * NL + l;
        const float4* pe = (const float4*)(emb + (size_t)pos_idx[gidx] * DIM);
        const float4* ne = (const float4*)(emb + (size_t)neg_idx[gidx] * DIM);

        float dp = 0.f, dn = 0.f;
#pragma unroll
        for (int q = 0; q < 4; ++q) {
            const int c4 = lane + q * 32;
            float4 g = __ldg((const float4*)gamma + c4);
            float4 be = __ldg((const float4*)beta + c4);
            float4 y;
            y.x = xv[q].x * rstd * g.x + be.x;
            y.y = xv[q].y * rstd * g.y + be.y;
            y.z = xv[q].z * rstd * g.z + be.z;
            y.w = xv[q].w * rstd * g.w + be.w;
            *(float4*)(yrow + c4 * 4) = y;
            float4 p = pe[c4], n = ne[c4];
            dp += y.x * p.x + y.y * p.y + y.z * p.z + y.w * p.w;
            dn += y.x * n.x + y.y * n.y + y.z * n.z + y.w * n.w;
        }
#pragma unroll
        for (int o = 16; o > 0; o >>= 1) {
            dp += __shfl_xor_sync(0xffffffffu, dp, o);
            dn += __shfl_xor_sync(0xffffffffu, dn, o);
        }
        if (lane == 0) {
            pos_out[m] = dp;
            neg_out[m] = dn;
        }
    }
}

// ================= launch =================
extern "C" void kernel_launch(void* const* d_in, const int* in_sizes, int n_in,
                              void* d_out, int out_size) {
    const float* X     = (const float*)d_in[0];   // log_feats [4,128,200,512]
    const float* Wm    = (const float*)d_in[1];   // W_maps [4,512,512]
    const float* bm    = (const float*)d_in[2];   // b_maps [4,512]
    const float* emb   = (const float*)d_in[3];   // emb_table [100002,512]
    const float* gamma = (const float*)d_in[4];   // [512]
    const float* beta  = (const float*)d_in[5];   // [512]
    const int*   lg    = (const int*)d_in[6];     // lg_dom [128,4,200]
    const int*   pos   = (const int*)d_in[7];     // pos_oth_dom [128,4,200]
    const int*   neg   = (const int*)d_in[8];     // neg_oth_dom [128,4,200]

    float* out     = (float*)d_out;
    float* mapped  = out;
    float* pos_out = out + (size_t)M_TOTAL * DIM;
    float* neg_out = pos_out + M_TOTAL;

    static bool attr_set = false;
    if (!attr_set) {
        cudaFuncSetAttribute(gemm_fused_kernel,
                             cudaFuncAttributeMaxDynamicSharedMemorySize,
                             SMEM_BYTES);
        attr_set = true;
    }

    reset_kernel<<<1, 1024>>>();
    route_kernel<<<(M_TOTAL + 255) / 256, 256>>>(lg);

    wconv_kernel<<<(ND * DIM * DIM / 8) / 256, 256>>>(Wm);
    {
        dim3 g((CAP * 64) / 256, ND);
        xconv_kernel<<<g, 256>>>(X);
    }

    dim3 grid(DIM / BN, MBLK, ND + 1);
    gemm_fused_kernel<<<grid, 256, SMEM_BYTES>>>(bm, emb, gamma, beta, pos, neg,
                                                 mapped, pos_out, neg_out);
}

// round 13
// speedup vs baseline: 1.4560x; 1.0194x over previous
#include <cuda_runtime.h>
#include <cuda_fp16.h>
#include <cstdint>
#include <cstddef>

#define ND 4
#define NB 128
#define NL 200
#define DIM 512
#define M_TOTAL (ND * NB * NL)   // 102400
#define LN_EPS 1e-8f

// GEMM tiling (R7 shape — do not shrink)
#define BM 128
#define BN 128
#define BK 32
#define NKT (DIM / BK)           // 16
#define NNB (DIM / BN)           // 4 n-blocks per m-block
#define ROW_B 80                 // padded row stride in bytes
#define STAGE_B (BM * ROW_B)     // 10240
#define NSTAGE 4
#define SMEM_BYTES (2 * NSTAGE * STAGE_B)   // 81920

// per-expert capacity (mean cnt ~20480, sd ~128)
#define CAP 24576
#define MBLK (CAP / BM)          // 192

// -------- device scratch (static, allocation-guard-safe) --------
__device__ int g_count[5];               // 4 experts + pad bucket
__device__ int g_list[5][M_TOTAL];
__device__ int g_arrive[ND][MBLK];
__device__ __half g_xh[ND][(size_t)CAP * DIM];   // 96 MB compacted fp16 X
__device__ __half g_wh[ND * DIM * DIM];          // 2 MB fp16 W

// -------- helpers --------
__device__ __forceinline__ unsigned pack_h2(float lo, float hi) {
    unsigned d;
    asm("cvt.rn.f16x2.f32 %0, %1, %2;" : "=r"(d) : "f"(hi), "f"(lo));
    return d;
}
__device__ __forceinline__ uint32_t smem_u32(const void* p) {
    uint32_t a;
    asm("{ .reg .u64 t; cvta.to.shared.u64 t, %1; cvt.u32.u64 %0, t; }" : "=r"(a) : "l"(p));
    return a;
}
#define CP_ASYNC16(dst, src) \
    asm volatile("cp.async.cg.shared.global [%0], [%1], 16;" :: "r"(dst), "l"(src) : "memory")
#define CP_COMMIT() asm volatile("cp.async.commit_group;" ::: "memory")
#define CP_WAIT2()  asm volatile("cp.async.wait_group 2;" ::: "memory")

#define LDMX4(r0, r1, r2, r3, a) \
    asm volatile("ldmatrix.sync.aligned.m8n8.x4.shared.b16 {%0,%1,%2,%3}, [%4];" \
        : "=r"(r0), "=r"(r1), "=r"(r2), "=r"(r3) : "r"(a))

__device__ __forceinline__ void mma_f16(float* d, const unsigned* a, const unsigned* b) {
    asm("mma.sync.aligned.m16n8k16.row.col.f32.f16.f16.f32 "
        "{%0,%1,%2,%3}, {%4,%5,%6,%7}, {%8,%9}, {%0,%1,%2,%3};"
        : "+f"(d[0]), "+f"(d[1]), "+f"(d[2]), "+f"(d[3])
        : "r"(a[0]), "r"(a[1]), "r"(a[2]), "r"(a[3]),
          "r"(b[0]), "r"(b[1]));
}

// ================= kernel 0: reset counters + arrival flags =================
__global__ void reset_kernel() {
    int t = threadIdx.x;
    if (t < 5) g_count[t] = 0;
    for (int i = t; i < ND * MBLK; i += blockDim.x)
        ((int*)g_arrive)[i] = 0;
}

// ================= kernel 1: routing (experts + pad bucket) =================
__global__ void route_kernel(const int* __restrict__ lg_dom) {
    int m = blockIdx.x * blockDim.x + threadIdx.x;
    if (m >= M_TOTAL) return;
    int i = m / (NB * NL);
    int r = m - i * (NB * NL);
    int b = r / NL;
    int l = r - b * NL;
    int lg = lg_dom[b * (ND * NL) + i * NL + l];
    int bucket = (lg > 0) ? (lg - 1) : 4;
    int slot = atomicAdd(&g_count[bucket], 1);
    g_list[bucket][slot] = m;
}

// ================= kernel 2: gather/compact/convert X + convert W =================
// y < ND: compacted fp16 X for expert y. y == ND: W conversion slice.
__global__ void xconv_kernel(const float* __restrict__ X, const float* __restrict__ W) {
    if (blockIdx.y == ND) {
        // W slice: ND*DIM*DIM/8 = 131072 threads needed -> 512 blocks
        if (blockIdx.x >= (ND * DIM * DIM / 8) / 256) return;
        int t = blockIdx.x * blockDim.x + threadIdx.x;
        const float4 v0 = ((const float4*)W)[t * 2];
        const float4 v1 = ((const float4*)W)[t * 2 + 1];
        uint4 o;
        o.x = pack_h2(v0.x, v0.y);
        o.y = pack_h2(v0.z, v0.w);
        o.z = pack_h2(v1.x, v1.y);
        o.w = pack_h2(v1.z, v1.w);
        ((uint4*)g_wh)[t] = o;
        return;
    }
    const int e = blockIdx.y;
    const int cnt = g_count[e];
    const int rcap = (cnt + BM - 1) & ~(BM - 1);
    const int t = blockIdx.x * blockDim.x + threadIdx.x;  // r * 64 + c
    const int r = t >> 6;
    if (r >= rcap) return;
    const int c = t & 63;
    uint4 o;
    if (r < cnt) {
        const float4* src = (const float4*)(X + (size_t)g_list[e][r] * DIM + c * 8);
        float4 v0 = src[0], v1 = src[1];
        o.x = pack_h2(v0.x, v0.y);
        o.y = pack_h2(v0.z, v0.w);
        o.z = pack_h2(v1.x, v1.y);
        o.w = pack_h2(v1.z, v1.w);
    } else {
        o = make_uint4(0u, 0u, 0u, 0u);
    }
    *(uint4*)(&g_xh[e][(size_t)r * DIM + c * 8]) = o;
}

// ================= kernel 3: GEMM + cross-CTA LN/logits + pad slice =================
// grid (NNB, MBLK, ND+1). z==0, x==0: pad-token slice (scheduled FIRST, overlaps
// the GEMM wave). z>=1: expert e = z-1 GEMM with cross-CTA LN epilogue.
__global__ void __launch_bounds__(256, 2)
gemm_fused_kernel(const float* __restrict__ Bias, const float* __restrict__ emb,
                  const float* __restrict__ gamma, const float* __restrict__ beta,
                  const int* __restrict__ pos_idx, const int* __restrict__ neg_idx,
                  float* __restrict__ Y, float* __restrict__ pos_out,
                  float* __restrict__ neg_out)
{
    const int mb  = blockIdx.y;
    const int tid  = threadIdx.x;
    const int lane = tid & 31;
    const int wid  = tid >> 5;

    // ---------------- pad-token slice (z == 0, runs first) ----------------
    if (blockIdx.z == 0) {
        if (blockIdx.x != 0) return;
        const int np = g_count[4];
        const int t0 = mb * BM;
        if (t0 >= np) return;
        for (int rr = 0; rr < 16; ++rr) {
            const int ti = t0 + wid * 16 + rr;
            if (ti >= np) break;          // warp-uniform
            int m = g_list[4][ti];
            int i = m / (NB * NL);
            int rm = m - i * (NB * NL);
            int b = rm / NL;
            int l = rm - b * NL;
            int gidx = b * (ND * NL) + i * NL + l;
            const float4* pe = (const float4*)(emb + (size_t)pos_idx[gidx] * DIM);
            const float4* ne = (const float4*)(emb + (size_t)neg_idx[gidx] * DIM);
            float4* yd = (float4*)(Y + (size_t)m * DIM);
            float dp = 0.f, dn = 0.f;
#pragma unroll
            for (int q = 0; q < 4; ++q) {
                const int c4 = lane + q * 32;
                float4 bv = __ldg((const float4*)beta + c4);
                yd[c4] = bv;
                float4 p = pe[c4], n = ne[c4];
                dp += bv.x * p.x + bv.y * p.y + bv.z * p.z + bv.w * p.w;
                dn += bv.x * n.x + bv.y * n.y + bv.z * n.z + bv.w * n.w;
            }
#pragma unroll
            for (int o = 16; o > 0; o >>= 1) {
                dp += __shfl_xor_sync(0xffffffffu, dp, o);
                dn += __shfl_xor_sync(0xffffffffu, dn, o);
            }
            if (lane == 0) {
                pos_out[m] = dp;
                neg_out[m] = dn;
            }
        }
        return;
    }

    // ---------------- GEMM path (expert e = z-1) ----------------
    const int e   = blockIdx.z - 1;
    const int cnt = g_count[e];
    const int m0  = mb * BM;
    if (m0 >= cnt) return;
    const int n0 = blockIdx.x * BN;
    const int* __restrict__ list = g_list[e];

    extern __shared__ char smem_c[];
    const uint32_t sbA = smem_u32(smem_c);
    const uint32_t sbB = sbA + NSTAGE * STAGE_B;

    const int warp_m = wid & 3;
    const int warp_n = wid >> 2;
    const int gr = lane >> 2;
    const int tc = lane & 3;

    // ---- cp.async loaders: 2 threads per row, 2 x 16B each ----
    const int l_row  = tid >> 1;
    const int l_half = tid & 1;
    const __half* a_g = &g_xh[e][(size_t)(m0 + l_row) * DIM + l_half * 16];
    const __half* b_g = g_wh + (size_t)e * DIM * DIM + (size_t)(n0 + l_row) * DIM + l_half * 16;
    const uint32_t dA0 = sbA + l_row * ROW_B + l_half * 32;
    const uint32_t dB0 = sbB + l_row * ROW_B + l_half * 32;

    auto issue = [&](int kt) {
        const int s = kt % NSTAGE;
        const int k0 = kt * BK;
        const uint32_t dA = dA0 + s * STAGE_B;
        const uint32_t dB = dB0 + s * STAGE_B;
        CP_ASYNC16(dA, a_g + k0);
        CP_ASYNC16(dA + 16, a_g + k0 + 8);
        CP_ASYNC16(dB, b_g + k0);
        CP_ASYNC16(dB + 16, b_g + k0 + 8);
    };

    const int lg8 = lane >> 3;
    const int lr8 = lane & 7;
    const uint32_t aLm = sbA + (warp_m * 32 + (lg8 & 1) * 8 + lr8) * ROW_B + (lg8 >> 1) * 16;
    const uint32_t bLm = sbB + (warp_n * 64 + ((lg8 >> 1) & 1) * 8 + lr8) * ROW_B + (lg8 & 1) * 16;

    float acc[2][8][4];
#pragma unroll
    for (int i = 0; i < 2; ++i)
#pragma unroll
        for (int j = 0; j < 8; ++j)
#pragma unroll
            for (int q = 0; q < 4; ++q) acc[i][j][q] = 0.f;

    issue(0); CP_COMMIT();
    issue(1); CP_COMMIT();
    issue(2); CP_COMMIT();

    // single-barrier k-loop
    for (int kt = 0; kt < NKT; ++kt) {
        CP_WAIT2();
        __syncthreads();
        if (kt + 3 < NKT) issue(kt + 3);
        CP_COMMIT();
        const int s = kt % NSTAGE;
        const uint32_t aS = aLm + s * STAGE_B;
        const uint32_t bS = bLm + s * STAGE_B;
#pragma unroll
        for (int ks = 0; ks < 2; ++ks) {
            unsigned afr[2][4], bfr[8][2];
#pragma unroll
            for (int i = 0; i < 2; ++i)
                LDMX4(afr[i][0], afr[i][1], afr[i][2], afr[i][3],
                      aS + i * 16 * ROW_B + ks * 32);
#pragma unroll
            for (int j = 0; j < 4; ++j)
                LDMX4(bfr[2 * j][0], bfr[2 * j][1], bfr[2 * j + 1][0], bfr[2 * j + 1][1],
                      bS + j * 16 * ROW_B + ks * 32);
#pragma unroll
            for (int i = 0; i < 2; ++i)
#pragma unroll
                for (int j = 0; j < 8; ++j)
                    mma_f16(acc[i][j], afr[i], bfr[j]);
        }
    }

    // ---- epilogue: bias add + scatter to gathered rows ----
#pragma unroll
    for (int i = 0; i < 2; ++i) {
        const int mr0 = m0 + warp_m * 32 + i * 16 + gr;
        const int mr1 = mr0 + 8;
        const bool v0 = (mr0 < cnt);
        const bool v1 = (mr1 < cnt);
        float* dst0 = v0 ? (Y + (size_t)list[mr0] * DIM + n0) : nullptr;
        float* dst1 = v1 ? (Y + (size_t)list[mr1] * DIM + n0) : nullptr;
#pragma unroll
        for (int j = 0; j < 8; ++j) {
            const int nf = warp_n * 64 + j * 8 + 2 * tc;
            float2 bv = *(const float2*)(Bias + e * DIM + n0 + nf);
            if (v0) {
                float2 o;
                o.x = acc[i][j][0] + bv.x;
                o.y = acc[i][j][1] + bv.y;
                *(float2*)(dst0 + nf) = o;
            }
            if (v1) {
                float2 o;
                o.x = acc[i][j][2] + bv.x;
                o.y = acc[i][j][3] + bv.y;
                *(float2*)(dst1 + nf) = o;
            }
        }
    }

    // ---- cross-CTA arrival: last n-block CTA runs LN + logits ----
    __threadfence();
    __shared__ int s_last;
    __syncthreads();
    if (tid == 0) {
        int old = atomicAdd(&g_arrive[e][mb], 1);
        s_last = (old == NNB - 1) ? 1 : 0;
    }
    __syncthreads();
    if (!s_last) return;
    __threadfence();   // acquire side

    // 8 warps x 16 rows, processed as 8 pairs (2-row ILP per iteration)
    for (int rr = 0; rr < 8; ++rr) {
        const int rw0 = wid * 16 + rr * 2;
        const int mi0 = m0 + rw0;
        if (mi0 >= cnt) break;         // warp-uniform
        const bool hv1 = (mi0 + 1 < cnt);
        const int ma = list[mi0];
        const int mb2 = hv1 ? list[mi0 + 1] : ma;
        float* ya = Y + (size_t)ma * DIM;
        float* yb = Y + (size_t)mb2 * DIM;

        // pass 1: both rows via L2, dual sums
        float4 xa[4], xb[4];
        float sa = 0.f, sb = 0.f;
#pragma unroll
        for (int q = 0; q < 4; ++q) {
            const int c4 = lane + q * 32;
            xa[q] = __ldcg((const float4*)(ya + c4 * 4));
            xb[q] = __ldcg((const float4*)(yb + c4 * 4));
            sa += xa[q].x + xa[q].y + xa[q].z + xa[q].w;
            sb += xb[q].x + xb[q].y + xb[q].z + xb[q].w;
        }
#pragma unroll
        for (int o = 16; o > 0; o >>= 1) {
            sa += __shfl_xor_sync(0xffffffffu, sa, o);
            sb += __shfl_xor_sync(0xffffffffu, sb, o);
        }
        const float mua = sa * (1.0f / DIM);
        const float mub = sb * (1.0f / DIM);

        float ssa = 0.f, ssb = 0.f;
#pragma unroll
        for (int q = 0; q < 4; ++q) {
            xa[q].x -= mua; xa[q].y -= mua; xa[q].z -= mua; xa[q].w -= mua;
            xb[q].x -= mub; xb[q].y -= mub; xb[q].z -= mub; xb[q].w -= mub;
            ssa += xa[q].x * xa[q].x + xa[q].y * xa[q].y
                 + xa[q].z * xa[q].z + xa[q].w * xa[q].w;
            ssb += xb[q].x * xb[q].x + xb[q].y * xb[q].y
                 + xb[q].z * xb[q].z + xb[q].w * xb[q].w;
        }
#pragma unroll
        for (int o = 16; o > 0; o >>= 1) {
            ssa += __shfl_xor_sync(0xffffffffu, ssa, o);
            ssb += __shfl_xor_sync(0xffffffffu, ssb, o);
        }
        const float rstda = rsqrtf(ssa * (1.0f / DIM) + LN_EPS);
        const float rstdb = rsqrtf(ssb * (1.0f / DIM) + LN_EPS);

        // logits indices for both rows
        int ia = ma / (NB * NL);
        int ra = ma - ia * (NB * NL);
        int ba = ra / NL;
        int la = ra - ba * NL;
        int gida = ba * (ND * NL) + ia * NL + la;
        int ib = mb2 / (NB * NL);
        int rb = mb2 - ib * (NB * NL);
        int bb2 = rb / NL;
        int lb = rb - bb2 * NL;
        int gidb = bb2 * (ND * NL) + ib * NL + lb;
        const float4* pea = (const float4*)(emb + (size_t)pos_idx[gida] * DIM);
        const float4* nea = (const float4*)(emb + (size_t)neg_idx[gida] * DIM);
        const float4* peb = (const float4*)(emb + (size_t)pos_idx[gidb] * DIM);
        const float4* neb = (const float4*)(emb + (size_t)neg_idx[gidb] * DIM);

        float dpa = 0.f, dna = 0.f, dpb = 0.f, dnb = 0.f;
#pragma unroll
        for (int q = 0; q < 4; ++q) {
            const int c4 = lane + q * 32;
            float4 g = __ldg((const float4*)gamma + c4);
            float4 be = __ldg((const float4*)beta + c4);
            float4 y0, y1;
            y0.x = xa[q].x * rstda * g.x + be.x;
            y0.y = xa[q].y * rstda * g.y + be.y;
            y0.z = xa[q].z * rstda * g.z + be.z;
            y0.w = xa[q].w * rstda * g.w + be.w;
            y1.x = xb[q].x * rstdb * g.x + be.x;
            y1.y = xb[q].y * rstdb * g.y + be.y;
            y1.z = xb[q].z * rstdb * g.z + be.z;
            y1.w = xb[q].w * rstdb * g.w + be.w;
            *(float4*)(ya + c4 * 4) = y0;
            if (hv1) *(float4*)(yb + c4 * 4) = y1;
            float4 pa = pea[c4], na = nea[c4];
            float4 pb = peb[c4], nb = neb[c4];
            dpa += y0.x * pa.x + y0.y * pa.y + y0.z * pa.z + y0.w * pa.w;
            dna += y0.x * na.x + y0.y * na.y + y0.z * na.z + y0.w * na.w;
            dpb += y1.x * pb.x + y1.y * pb.y + y1.z * pb.z + y1.w * pb.w;
            dnb += y1.x * nb.x + y1.y * nb.y + y1.z * nb.z + y1.w * nb.w;
        }
#pragma unroll
        for (int o = 16; o > 0; o >>= 1) {
            dpa += __shfl_xor_sync(0xffffffffu, dpa, o);
            dna += __shfl_xor_sync(0xffffffffu, dna, o);
            dpb += __shfl_xor_sync(0xffffffffu, dpb, o);
            dnb += __shfl_xor_sync(0xffffffffu, dnb, o);
        }
        if (lane == 0) {
            pos_out[ma] = dpa;
            neg_out[ma] = dna;
            if (hv1) {
                pos_out[mb2] = dpb;
                neg_out[mb2] = dnb;
            }
        }
    }
}

// ================= launch =================
extern "C" void kernel_launch(void* const* d_in, const int* in_sizes, int n_in,
                              void* d_out, int out_size) {
    const float* X     = (const float*)d_in[0];   // log_feats [4,128,200,512]
    const float* Wm    = (const float*)d_in[1];   // W_maps [4,512,512]
    const float* bm    = (const float*)d_in[2];   // b_maps [4,512]
    const float* emb   = (const float*)d_in[3];   // emb_table [100002,512]
    const float* gamma = (const float*)d_in[4];   // [512]
    const float* beta  = (const float*)d_in[5];   // [512]
    const int*   lg    = (const int*)d_in[6];     // lg_dom [128,4,200]
    const int*   pos   = (const int*)d_in[7];     // pos_oth_dom [128,4,200]
    const int*   neg   = (const int*)d_in[8];     // neg_oth_dom [128,4,200]

    float* out     = (float*)d_out;
    float* mapped  = out;
    float* pos_out = out + (size_t)M_TOTAL * DIM;
    float* neg_out = pos_out + M_TOTAL;

    static bool attr_set = false;
    if (!attr_set) {
        cudaFuncSetAttribute(gemm_fused_kernel,
                             cudaFuncAttributeMaxDynamicSharedMemorySize,
                             SMEM_BYTES);
        attr_set = true;
    }

    reset_kernel<<<1, 1024>>>();
    route_kernel<<<(M_TOTAL + 255) / 256, 256>>>(lg);

    {
        dim3 g((CAP * 64) / 256, ND + 1);   // y==ND slice converts W
        xconv_kernel<<<g, 256>>>(X, Wm);
    }

    dim3 grid(DIM / BN, MBLK, ND + 1);
    gemm_fused_kernel<<<grid, 256, SMEM_BYTES>>>(bm, emb, gamma, beta, pos, neg,
                                                 mapped, pos_out, neg_out);
}